// round 4
// baseline (speedup 1.0000x reference)
#include <cuda_runtime.h>
#include <math.h>

// Problem constants
#define BB   2
#define SS   2048
#define DDIM 2048
#define HH   16
#define HDIM 128
#define FFD  5632
#define BSR  (BB * SS)          // 4096 rows total
#define EPSV 1e-5f

// ---------------------------------------------------------------------------
// Scratch (static device globals — no allocations allowed)
// ---------------------------------------------------------------------------
__device__ float g_xn  [BSR * DDIM];
__device__ float g_yn  [BSR * DDIM];
__device__ float g_q   [BSR * DDIM];
__device__ float g_k   [BSR * DDIM];
__device__ float g_v   [BSR * DDIM];
__device__ float g_att [BSR * DDIM];
__device__ float g_proj[BSR * DDIM];
__device__ float g_h1  [BSR * FFD];
__device__ float g_h3  [BSR * FFD];
__device__ float g_ff  [BSR * DDIM];

// ---------------------------------------------------------------------------
// RMSNorm: out[row] = in[row] * rsqrt(mean(in^2)+eps) * w
// grid = BSR blocks, 256 threads, each thread handles 8 contiguous floats
// ---------------------------------------------------------------------------
__global__ __launch_bounds__(256) void rmsnorm_kernel(
    const float* __restrict__ in, const float* __restrict__ w,
    float* __restrict__ out)
{
    const int row  = blockIdx.x;
    const int base = threadIdx.x * 8;
    const float* r = in + (size_t)row * DDIM;

    float v[8];
    *(float4*)(v)     = *(const float4*)(r + base);
    *(float4*)(v + 4) = *(const float4*)(r + base + 4);

    float ss = 0.f;
#pragma unroll
    for (int i = 0; i < 8; i++) ss += v[i] * v[i];
#pragma unroll
    for (int o = 16; o > 0; o >>= 1) ss += __shfl_xor_sync(0xffffffffu, ss, o);

    __shared__ float red[8];
    __shared__ float sscale;
    if ((threadIdx.x & 31) == 0) red[threadIdx.x >> 5] = ss;
    __syncthreads();
    if (threadIdx.x == 0) {
        float t = 0.f;
#pragma unroll
        for (int i = 0; i < 8; i++) t += red[i];
        sscale = rsqrtf(t / (float)DDIM + EPSV);
    }
    __syncthreads();
    const float sc = sscale;

    float o8[8];
#pragma unroll
    for (int i = 0; i < 8; i++) o8[i] = v[i] * sc * w[base + i];
    float* op = out + (size_t)row * DDIM + base;
    *(float4*)(op)     = *(float4*)(o8);
    *(float4*)(op + 4) = *(float4*)(o8 + 4);
}

// ---------------------------------------------------------------------------
// RMSNorm of (ff + residual), writes final output
// ---------------------------------------------------------------------------
__global__ __launch_bounds__(256) void rms_resid_out_kernel(
    const float* __restrict__ ff, const float* __restrict__ res,
    const float* __restrict__ w, float* __restrict__ out)
{
    const int row  = blockIdx.x;
    const int base = threadIdx.x * 8;
    const float* f = ff  + (size_t)row * DDIM;
    const float* r = res + (size_t)row * DDIM;

    float4 a0 = *(const float4*)(f + base);
    float4 a1 = *(const float4*)(f + base + 4);
    float4 b0 = *(const float4*)(r + base);
    float4 b1 = *(const float4*)(r + base + 4);

    float v[8];
    v[0] = a0.x + b0.x; v[1] = a0.y + b0.y; v[2] = a0.z + b0.z; v[3] = a0.w + b0.w;
    v[4] = a1.x + b1.x; v[5] = a1.y + b1.y; v[6] = a1.z + b1.z; v[7] = a1.w + b1.w;

    float ss = 0.f;
#pragma unroll
    for (int i = 0; i < 8; i++) ss += v[i] * v[i];
#pragma unroll
    for (int o = 16; o > 0; o >>= 1) ss += __shfl_xor_sync(0xffffffffu, ss, o);

    __shared__ float red[8];
    __shared__ float sscale;
    if ((threadIdx.x & 31) == 0) red[threadIdx.x >> 5] = ss;
    __syncthreads();
    if (threadIdx.x == 0) {
        float t = 0.f;
#pragma unroll
        for (int i = 0; i < 8; i++) t += red[i];
        sscale = rsqrtf(t / (float)DDIM + EPSV);
    }
    __syncthreads();
    const float sc = sscale;

    float o8[8];
#pragma unroll
    for (int i = 0; i < 8; i++) o8[i] = v[i] * sc * w[base + i];
    float* op = out + (size_t)row * DDIM + base;
    *(float4*)(op)     = *(float4*)(o8);
    *(float4*)(op + 4) = *(float4*)(o8 + 4);
}

// ---------------------------------------------------------------------------
// SGEMM (NT): C[M,N] = A[M,K] * B[N,K]^T,  row-major, all dims multiples of
// the tile sizes. 128x128 tile, BK=8, 256 threads, 8x8 microtile/thread.
// SMEM stored K-major with padded stride 132 -> conflict-free LDS.128.
// ---------------------------------------------------------------------------
#define TBK 8
#define SLD 132

__global__ __launch_bounds__(256, 2) void sgemm_nt(
    const float* __restrict__ A, const float* __restrict__ B,
    float* __restrict__ C, int M, int N, int K)
{
    __shared__ float As[TBK * SLD];
    __shared__ float Bs[TBK * SLD];

    const int tid = threadIdx.x;
    const int tx  = tid & 15;        // 0..15 -> N microtile
    const int ty  = tid >> 4;        // 0..15 -> M microtile
    const int bm  = blockIdx.y * 128;
    const int bn  = blockIdx.x * 128;

    const int lrow = tid >> 1;       // 0..127
    const int lk   = (tid & 1) * 4;  // 0 or 4
    const float* Ap = A + (size_t)(bm + lrow) * K + lk;
    const float* Bp = B + (size_t)(bn + lrow) * K + lk;

    float acc[8][8];
#pragma unroll
    for (int i = 0; i < 8; i++)
#pragma unroll
        for (int j = 0; j < 8; j++) acc[i][j] = 0.f;

    for (int k0 = 0; k0 < K; k0 += TBK) {
        float4 av = *(const float4*)(Ap + k0);
        float4 bv = *(const float4*)(Bp + k0);
        __syncthreads();
        As[(lk + 0) * SLD + lrow] = av.x;
        As[(lk + 1) * SLD + lrow] = av.y;
        As[(lk + 2) * SLD + lrow] = av.z;
        As[(lk + 3) * SLD + lrow] = av.w;
        Bs[(lk + 0) * SLD + lrow] = bv.x;
        Bs[(lk + 1) * SLD + lrow] = bv.y;
        Bs[(lk + 2) * SLD + lrow] = bv.z;
        Bs[(lk + 3) * SLD + lrow] = bv.w;
        __syncthreads();

#pragma unroll
        for (int kk = 0; kk < TBK; kk++) {
            float a[8], b[8];
            *(float4*)(a)     = *(const float4*)(As + kk * SLD + ty * 4);
            *(float4*)(a + 4) = *(const float4*)(As + kk * SLD + 64 + ty * 4);
            *(float4*)(b)     = *(const float4*)(Bs + kk * SLD + tx * 4);
            *(float4*)(b + 4) = *(const float4*)(Bs + kk * SLD + 64 + tx * 4);
#pragma unroll
            for (int i = 0; i < 8; i++)
#pragma unroll
                for (int j = 0; j < 8; j++)
                    acc[i][j] += a[i] * b[j];
        }
    }

#pragma unroll
    for (int i = 0; i < 8; i++) {
        const int m = bm + ((i < 4) ? (ty * 4 + i) : (64 + ty * 4 + (i - 4)));
        float4 c0 = make_float4(acc[i][0], acc[i][1], acc[i][2], acc[i][3]);
        float4 c1 = make_float4(acc[i][4], acc[i][5], acc[i][6], acc[i][7]);
        float* crow = C + (size_t)m * N + bn;
        *(float4*)(crow + tx * 4)      = c0;
        *(float4*)(crow + 64 + tx * 4) = c1;
    }
}

// ---------------------------------------------------------------------------
// SiLU-mul:  h1 = silu(h1) * h3   (vectorized elementwise)
// ---------------------------------------------------------------------------
__global__ __launch_bounds__(256) void silu_mul_kernel(
    float* __restrict__ h1, const float* __restrict__ h3, int n4)
{
    const int i = blockIdx.x * blockDim.x + threadIdx.x;
    if (i >= n4) return;
    float4 a = ((float4*)h1)[i];
    float4 b = ((const float4*)h3)[i];
    a.x = a.x * (1.f / (1.f + __expf(-a.x))) * b.x;
    a.y = a.y * (1.f / (1.f + __expf(-a.y))) * b.y;
    a.z = a.z * (1.f / (1.f + __expf(-a.z))) * b.z;
    a.w = a.w * (1.f / (1.f + __expf(-a.w))) * b.w;
    ((float4*)h1)[i] = a;
}

// ---------------------------------------------------------------------------
// Flash attention (fp32, non-tensorcore).
// Q,K,V,O: (BSR, DDIM) row-major; head h occupies cols [h*128, (h+1)*128).
// Block: one 64-row Q tile of one (b,h); loops over 32 kv tiles of 64 rows.
// Threads 256 as 16x16 grid:
//   score microtile: rows {i*16+ty}, cols {j*16+tx}  (interleaved -> no
//   LDS.128 bank conflicts with row stride 132)
//   O microtile:     rows {i*16+ty}, cols {tx*4+jd, 64+tx*4+jd}
// Dynamic SMEM: sQ[64][132] + sK[64][132] + sV[64][128] + sP[64][65] = 116992 B
// ---------------------------------------------------------------------------
#define FLASH_SMEM ((64*132 + 64*132 + 64*128 + 64*65) * 4)

__global__ __launch_bounds__(256, 1) void flash_kernel(
    const float* __restrict__ Qg, const float* __restrict__ Kg,
    const float* __restrict__ Vg, float* __restrict__ Og)
{
    extern __shared__ float sm[];
    float* sQ = sm;                  // [64][132]
    float* sK = sm + 64 * 132;       // [64][132]
    float* sV = sK + 64 * 132;       // [64][128]
    float* sP = sV + 64 * 128;       // [64][65]

    const int tid = threadIdx.x;
    const int tx  = tid & 15;
    const int ty  = tid >> 4;
    const int q0  = blockIdx.x * 64;
    const int h   = blockIdx.y;
    const int b   = blockIdx.z;
    const size_t rowbase = (size_t)b * SS;
    const float scale = 0.0883883476483184405f;   // 1/sqrt(128)

    // Load Q tile (coalesced global, conflict-free smem store)
    {
        const float* Qp = Qg + (rowbase + q0) * DDIM + h * HDIM;
#pragma unroll
        for (int li = tid; li < 64 * 32; li += 256) {
            int r = li >> 5, c4 = li & 31;
            *(float4*)(sQ + r * 132 + c4 * 4) =
                *(const float4*)(Qp + (size_t)r * DDIM + c4 * 4);
        }
    }

    float m_i[4], l_i[4], o[4][8];
#pragma unroll
    for (int i = 0; i < 4; i++) {
        m_i[i] = -1e30f;
        l_i[i] = 0.f;
#pragma unroll
        for (int d = 0; d < 8; d++) o[i][d] = 0.f;
    }

    for (int t = 0; t < SS / 64; t++) {
        const float* Kp = Kg + (rowbase + t * 64) * DDIM + h * HDIM;
        const float* Vp = Vg + (rowbase + t * 64) * DDIM + h * HDIM;

        __syncthreads();   // previous iteration's consumers done (also covers Q)
#pragma unroll
        for (int li = tid; li < 64 * 32; li += 256) {
            int r = li >> 5, c4 = li & 31;
            *(float4*)(sK + r * 132 + c4 * 4) =
                *(const float4*)(Kp + (size_t)r * DDIM + c4 * 4);
            *(float4*)(sV + r * 128 + c4 * 4) =
                *(const float4*)(Vp + (size_t)r * DDIM + c4 * 4);
        }
        __syncthreads();

        // ---- scores: s[i][j] = Q[i*16+ty] . K[j*16+tx] ----
        float s[4][4];
#pragma unroll
        for (int i = 0; i < 4; i++)
#pragma unroll
            for (int j = 0; j < 4; j++) s[i][j] = 0.f;

#pragma unroll 4
        for (int c4 = 0; c4 < 32; c4++) {
            float4 qv[4], kv[4];
#pragma unroll
            for (int i = 0; i < 4; i++)
                qv[i] = *(const float4*)(sQ + (i * 16 + ty) * 132 + c4 * 4);
#pragma unroll
            for (int j = 0; j < 4; j++)
                kv[j] = *(const float4*)(sK + (j * 16 + tx) * 132 + c4 * 4);
#pragma unroll
            for (int i = 0; i < 4; i++)
#pragma unroll
                for (int j = 0; j < 4; j++)
                    s[i][j] += qv[i].x * kv[j].x + qv[i].y * kv[j].y +
                               qv[i].z * kv[j].z + qv[i].w * kv[j].w;
        }

        // ---- online softmax update ----
#pragma unroll
        for (int i = 0; i < 4; i++) {
            float mx = -1e30f;
#pragma unroll
            for (int j = 0; j < 4; j++) {
                s[i][j] *= scale;
                mx = fmaxf(mx, s[i][j]);
            }
#pragma unroll
            for (int w = 1; w < 16; w <<= 1)
                mx = fmaxf(mx, __shfl_xor_sync(0xffffffffu, mx, w));
            const float mnew  = fmaxf(m_i[i], mx);
            const float alpha = __expf(m_i[i] - mnew);
            float rs = 0.f;
#pragma unroll
            for (int j = 0; j < 4; j++) {
                float p = __expf(s[i][j] - mnew);
                sP[(i * 16 + ty) * 65 + j * 16 + tx] = p;
                rs += p;
            }
#pragma unroll
            for (int w = 1; w < 16; w <<= 1)
                rs += __shfl_xor_sync(0xffffffffu, rs, w);
            l_i[i] = l_i[i] * alpha + rs;
            m_i[i] = mnew;
#pragma unroll
            for (int d = 0; d < 8; d++) o[i][d] *= alpha;
        }
        __syncthreads();   // sP fully written

        // ---- O += P @ V ----
#pragma unroll 4
        for (int j = 0; j < 64; j++) {
            float4 v0 = *(const float4*)(sV + j * 128 + tx * 4);
            float4 v1 = *(const float4*)(sV + j * 128 + 64 + tx * 4);
#pragma unroll
            for (int i = 0; i < 4; i++) {
                const float p = sP[(i * 16 + ty) * 65 + j];
                o[i][0] += p * v0.x; o[i][1] += p * v0.y;
                o[i][2] += p * v0.z; o[i][3] += p * v0.w;
                o[i][4] += p * v1.x; o[i][5] += p * v1.y;
                o[i][6] += p * v1.z; o[i][7] += p * v1.w;
            }
        }
    }

    // ---- normalize and write out ----
#pragma unroll
    for (int i = 0; i < 4; i++) {
        const float inv = 1.f / l_i[i];
        float* op = Og + (rowbase + q0 + i * 16 + ty) * DDIM + h * HDIM;
        float4 r0 = make_float4(o[i][0] * inv, o[i][1] * inv, o[i][2] * inv, o[i][3] * inv);
        float4 r1 = make_float4(o[i][4] * inv, o[i][5] * inv, o[i][6] * inv, o[i][7] * inv);
        *(float4*)(op + tx * 4)      = r0;
        *(float4*)(op + 64 + tx * 4) = r1;
    }
}

// ---------------------------------------------------------------------------
// Host orchestration
// ---------------------------------------------------------------------------
extern "C" void kernel_launch(void* const* d_in, const int* in_sizes, int n_in,
                              void* d_out, int out_size)
{
    (void)in_sizes; (void)n_in; (void)out_size;

    const float* x           = (const float*)d_in[0];
    const float* y           = (const float*)d_in[1];
    const float* attn_norm_w = (const float*)d_in[2];
    const float* wq[2]  = {(const float*)d_in[3],  (const float*)d_in[7]};
    const float* wk[2]  = {(const float*)d_in[4],  (const float*)d_in[8]};
    const float* wv[2]  = {(const float*)d_in[5],  (const float*)d_in[9]};
    const float* wo[2]  = {(const float*)d_in[6],  (const float*)d_in[10]};
    const float* w1[2]  = {(const float*)d_in[11], (const float*)d_in[15]};
    const float* w2[2]  = {(const float*)d_in[12], (const float*)d_in[16]};
    const float* w3[2]  = {(const float*)d_in[13], (const float*)d_in[17]};
    const float* fnw[2] = {(const float*)d_in[14], (const float*)d_in[18]};
    float* out = (float*)d_out;

    float *xn, *yn, *q, *k, *v, *att, *proj, *h1, *h3, *ff;
    cudaGetSymbolAddress((void**)&xn,   g_xn);
    cudaGetSymbolAddress((void**)&yn,   g_yn);
    cudaGetSymbolAddress((void**)&q,    g_q);
    cudaGetSymbolAddress((void**)&k,    g_k);
    cudaGetSymbolAddress((void**)&v,    g_v);
    cudaGetSymbolAddress((void**)&att,  g_att);
    cudaGetSymbolAddress((void**)&proj, g_proj);
    cudaGetSymbolAddress((void**)&h1,   g_h1);
    cudaGetSymbolAddress((void**)&h3,   g_h3);
    cudaGetSymbolAddress((void**)&ff,   g_ff);

    cudaFuncSetAttribute(flash_kernel,
                         cudaFuncAttributeMaxDynamicSharedMemorySize, FLASH_SMEM);

    // Pre-norms (shared attn_norm weight)
    rmsnorm_kernel<<<BSR, 256>>>(x, attn_norm_w, xn);
    rmsnorm_kernel<<<BSR, 256>>>(y, attn_norm_w, yn);

    const dim3 gProj(DDIM / 128, BSR / 128);   // 16 x 32
    const dim3 gFF  (FFD  / 128, BSR / 128);   // 44 x 32
    const dim3 gAttn(SS / 64, HH, BB);         // 32 x 16 x 2
    const int  n4 = BSR * FFD / 4;

    for (int p = 0; p < 2; p++) {
        const float* qin   = (p == 0) ? xn : yn;
        const float* kvin  = (p == 0) ? yn : xn;
        const float* resid = (p == 0) ? x  : y;

        sgemm_nt<<<gProj, 256>>>(qin,  wq[p], q, BSR, DDIM, DDIM);
        sgemm_nt<<<gProj, 256>>>(kvin, wk[p], k, BSR, DDIM, DDIM);
        sgemm_nt<<<gProj, 256>>>(kvin, wv[p], v, BSR, DDIM, DDIM);

        flash_kernel<<<gAttn, 256, FLASH_SMEM>>>(q, k, v, att);

        sgemm_nt<<<gProj, 256>>>(att, wo[p], proj, BSR, DDIM, DDIM);

        sgemm_nt<<<gFF, 256>>>(proj, w1[p], h1, BSR, FFD, DDIM);
        sgemm_nt<<<gFF, 256>>>(proj, w3[p], h3, BSR, FFD, DDIM);
        silu_mul_kernel<<<(n4 + 255) / 256, 256>>>(h1, h3, n4);
        sgemm_nt<<<gProj, 256>>>(h1, w2[p], ff, BSR, DDIM, FFD);

        rms_resid_out_kernel<<<BSR, 256>>>(ff, resid, fnw[p],
                                           out + (size_t)p * BSR * DDIM);
    }
}

// round 7
// speedup vs baseline: 1.6617x; 1.6617x over previous
#include <cuda_runtime.h>
#include <cuda_bf16.h>
#include <math.h>
#include <stdint.h>

// Problem constants
#define BB   2
#define SS   2048
#define DDIM 2048
#define HH   16
#define HDIM 128
#define FFD  5632
#define BSR  (BB * SS)          // 4096 rows total
#define EPSV 1e-5f

// Feature gate: tcgen05 only exists when a real sm_103a device pass runs.
#if defined(__CUDA_ARCH__) && defined(__CUDA_ARCH_FEAT_SM103_ALL)
#define HAS_TCGEN05 1
#else
#define HAS_TCGEN05 0
#endif

// ---------------------------------------------------------------------------
// Scratch (static device globals — no allocations allowed)
// ---------------------------------------------------------------------------
__device__ float g_xn  [BSR * DDIM];
__device__ float g_yn  [BSR * DDIM];
__device__ float g_q   [BSR * DDIM];
__device__ float g_k   [BSR * DDIM];
__device__ float g_v   [BSR * DDIM];
__device__ float g_att [BSR * DDIM];
__device__ float g_proj[BSR * DDIM];
__device__ float g_h1  [BSR * FFD];
__device__ float g_h3  [BSR * FFD];
__device__ float g_ff  [BSR * DDIM];

// bf16 split buffers (hi/lo), reused across GEMMs
__device__ __nv_bfloat16 g_act_hi[BSR * FFD];
__device__ __nv_bfloat16 g_act_lo[BSR * FFD];
__device__ __nv_bfloat16 g_wgt_hi[FFD * DDIM];
__device__ __nv_bfloat16 g_wgt_lo[FFD * DDIM];

// ---------------------------------------------------------------------------
// PTX helpers. tcgen05 asm is emitted ONLY under HAS_TCGEN05 so the
// compute_103 (non-'a') device pass compiles cleanly.
// ---------------------------------------------------------------------------
__device__ __forceinline__ uint32_t smem_u32(const void* p) {
    uint32_t a;
    asm("{ .reg .u64 t; cvta.to.shared.u64 t, %1; cvt.u32.u64 %0, t; }" : "=r"(a) : "l"(p));
    return a;
}
__device__ __forceinline__ uint32_t elect_one() {
    uint32_t p;
    asm volatile("{\n\t.reg .pred p;\n\telect.sync _|p, 0xFFFFFFFF;\n\tselp.b32 %0, 1, 0, p;\n\t}" : "=r"(p));
    return p;
}
__device__ __forceinline__ void mbar_init(uint32_t a, uint32_t cnt) {
    asm volatile("mbarrier.init.shared.b64 [%0], %1;" :: "r"(a), "r"(cnt) : "memory");
}
__device__ __forceinline__ void mbar_wait(uint32_t a, uint32_t parity) {
    asm volatile(
        "{\n\t.reg .pred P;\n\t"
        "WL%=:\n\t"
        "mbarrier.try_wait.parity.acquire.cta.shared::cta.b64 P, [%0], %1, 0x989680;\n\t"
        "@P bra.uni WD%=;\n\t"
        "bra.uni WL%=;\n\t"
        "WD%=:\n\t}"
        :: "r"(a), "r"(parity) : "memory");
}
__device__ __forceinline__ void tc_alloc(uint32_t smem_dst, uint32_t ncols) {
#if HAS_TCGEN05
    asm volatile("tcgen05.alloc.cta_group::1.sync.aligned.shared::cta.b32 [%0], %1;"
                 :: "r"(smem_dst), "r"(ncols) : "memory");
#endif
}
__device__ __forceinline__ void tc_dealloc(uint32_t tmem, uint32_t ncols) {
#if HAS_TCGEN05
    asm volatile("tcgen05.dealloc.cta_group::1.sync.aligned.b32 %0, %1;" :: "r"(tmem), "r"(ncols));
#endif
}
__device__ __forceinline__ void tc_relinquish() {
#if HAS_TCGEN05
    asm volatile("tcgen05.relinquish_alloc_permit.cta_group::1.sync.aligned;");
#endif
}
__device__ __forceinline__ void tc_commit(uint32_t mbar) {
#if HAS_TCGEN05
    asm volatile("tcgen05.commit.cta_group::1.mbarrier::arrive::one.shared::cluster.b64 [%0];"
                 :: "r"(mbar) : "memory");
#endif
}
__device__ __forceinline__ void tc_mma_f16_ss(uint32_t d, uint64_t ad, uint64_t bd,
                                              uint32_t idesc, bool acc) {
#if HAS_TCGEN05
    uint32_t en = acc ? 1u : 0u;
    asm volatile(
        "{\n\t.reg .pred p;\n\tsetp.ne.u32 p, %5, 0;\n\t"
        "tcgen05.mma.cta_group::1.kind::f16 [%0], %1, %2, %3, {%4, %4, %4, %4}, p;\n\t}"
        :: "r"(d), "l"(ad), "l"(bd), "r"(idesc), "r"(0u), "r"(en) : "memory");
#endif
}
__device__ __forceinline__ void fence_proxy_async_shared() {
#if HAS_TCGEN05
    asm volatile("fence.proxy.async.shared::cta;" ::: "memory");
#endif
}
__device__ __forceinline__ void tc_fence_after() {
#if HAS_TCGEN05
    asm volatile("tcgen05.fence::after_thread_sync;" ::: "memory");
#endif
}
__device__ __forceinline__ void tc_fence_before() {
#if HAS_TCGEN05
    asm volatile("tcgen05.fence::before_thread_sync;" ::: "memory");
#endif
}
__device__ __forceinline__ void tc_wait_ld() {
#if HAS_TCGEN05
    asm volatile("tcgen05.wait::ld.sync.aligned;" ::: "memory");
#endif
}
__device__ __forceinline__ void tc_ld_x32(uint32_t* r, uint32_t tmem) {
#if HAS_TCGEN05
    asm volatile(
        "tcgen05.ld.sync.aligned.32x32b.x32.b32 "
        "{%0, %1, %2, %3, %4, %5, %6, %7, "
        " %8, %9, %10, %11, %12, %13, %14, %15, "
        " %16, %17, %18, %19, %20, %21, %22, %23, "
        " %24, %25, %26, %27, %28, %29, %30, %31}, [%32];"
        : "=r"(r[0]),  "=r"(r[1]),  "=r"(r[2]),  "=r"(r[3]),
          "=r"(r[4]),  "=r"(r[5]),  "=r"(r[6]),  "=r"(r[7]),
          "=r"(r[8]),  "=r"(r[9]),  "=r"(r[10]), "=r"(r[11]),
          "=r"(r[12]), "=r"(r[13]), "=r"(r[14]), "=r"(r[15]),
          "=r"(r[16]), "=r"(r[17]), "=r"(r[18]), "=r"(r[19]),
          "=r"(r[20]), "=r"(r[21]), "=r"(r[22]), "=r"(r[23]),
          "=r"(r[24]), "=r"(r[25]), "=r"(r[26]), "=r"(r[27]),
          "=r"(r[28]), "=r"(r[29]), "=r"(r[30]), "=r"(r[31])
        : "r"(tmem));
#endif
}

// Baseline-PTX bf16 MMA (sm_80+; valid on compute_103) — fallback path.
__device__ __forceinline__ void mma_bf16(float* d, const uint32_t* a, const uint32_t* b) {
    asm volatile(
        "mma.sync.aligned.m16n8k16.row.col.f32.bf16.bf16.f32 "
        "{%0,%1,%2,%3}, {%4,%5,%6,%7}, {%8,%9}, {%0,%1,%2,%3};"
        : "+f"(d[0]), "+f"(d[1]), "+f"(d[2]), "+f"(d[3])
        : "r"(a[0]), "r"(a[1]), "r"(a[2]), "r"(a[3]), "r"(b[0]), "r"(b[1]));
}

// Swizzled LDS.32 from a 128-rows x 128B tile (XOR-16B swizzle, bank-conflict free)
__device__ __forceinline__ uint32_t lds_sw(const char* base, int row, int kbyte) {
    uint32_t cb = (uint32_t)kbyte ^ (((uint32_t)row & 7u) << 4);
    return *(const uint32_t*)(base + row * 128 + cb);
}

// 64-bit SMEM descriptor: SW128, Blackwell version=1, LBO=1, SBO=64 (K-major, 128B rows)
#define SMEM_DESC_BASE ((2ull << 61) | (1ull << 46) | (64ull << 32) | (1ull << 16))
#define MK_DESC(addr)  (SMEM_DESC_BASE | ((uint64_t)((addr) >> 4) & 0x3FFFull))

// ---------------------------------------------------------------------------
// fp32 -> bf16 hi/lo split conversion (vectorized x4)
// ---------------------------------------------------------------------------
__global__ __launch_bounds__(256) void split_bf16_kernel(
    const float* __restrict__ in, __nv_bfloat16* __restrict__ hi,
    __nv_bfloat16* __restrict__ lo, int n4)
{
    const int i = blockIdx.x * 256 + threadIdx.x;
    if (i >= n4) return;
    float4 v = ((const float4*)in)[i];
    __nv_bfloat16 h0 = __float2bfloat16(v.x);
    __nv_bfloat16 h1 = __float2bfloat16(v.y);
    __nv_bfloat16 h2 = __float2bfloat16(v.z);
    __nv_bfloat16 h3 = __float2bfloat16(v.w);
    __nv_bfloat16 l0 = __float2bfloat16(v.x - __bfloat162float(h0));
    __nv_bfloat16 l1 = __float2bfloat16(v.y - __bfloat162float(h1));
    __nv_bfloat16 l2 = __float2bfloat16(v.z - __bfloat162float(h2));
    __nv_bfloat16 l3 = __float2bfloat16(v.w - __bfloat162float(h3));
    ((__nv_bfloat162*)hi)[2 * i]     = __nv_bfloat162(h0, h1);
    ((__nv_bfloat162*)hi)[2 * i + 1] = __nv_bfloat162(h2, h3);
    ((__nv_bfloat162*)lo)[2 * i]     = __nv_bfloat162(l0, l1);
    ((__nv_bfloat162*)lo)[2 * i + 1] = __nv_bfloat162(l2, l3);
}

// ---------------------------------------------------------------------------
// bf16x3 GEMM: C[M,N] = A[M,K] @ B[N,K]^T (fp32 result).
// C += Ah*Bh + Ah*Bl + Al*Bh, fp32 accumulate.
// Tile 128x128 per CTA, Kc=64 (128B rows, SW128 layout), double-buffered SMEM.
// Path A (HAS_TCGEN05): SS-mode tcgen05 MMA into TMEM, mbarrier-paced.
// Path B (fallback):    mma.sync.m16n8k16 bf16, 4 warps x (32M x 128N).
// ---------------------------------------------------------------------------
#define GEMM_TILE_BYTES 16384
#define GEMM_BUF_BYTES  (4 * GEMM_TILE_BYTES)
#define GEMM_SMEM       (2 * GEMM_BUF_BYTES + 1024)

// idesc: kind::f16, dtype F32, a/b BF16 K-major, M=128, N=128
#define GEMM_IDESC ((1u << 4) | (1u << 7) | (1u << 10) | ((128u / 8) << 17) | ((128u / 16) << 24))

__global__ __launch_bounds__(128, 1)
void gemm_bf16x3(const __nv_bfloat16* __restrict__ Ah, const __nv_bfloat16* __restrict__ Al,
                 const __nv_bfloat16* __restrict__ Bh, const __nv_bfloat16* __restrict__ Bl,
                 float* __restrict__ C, int M, int N, int K)
{
    extern __shared__ char dyn[];
    __shared__ uint32_t s_tmem[1];
    __shared__ __align__(8) unsigned long long s_mbar[2];

    const int tid  = threadIdx.x;
    const int wid  = tid >> 5;
    const int lane = tid & 31;
    const int bm   = blockIdx.y * 128;
    const int bn   = blockIdx.x * 128;

    const uint32_t dyn_u   = smem_u32(dyn);
    const uint32_t tile_u  = (dyn_u + 1023u) & ~1023u;       // 1024-aligned tile base
    char* tile_p           = dyn + (tile_u - dyn_u);
    const uint32_t mbar_u  = smem_u32(&s_mbar[0]);
    const uint32_t tptr_u  = smem_u32(&s_tmem[0]);

    const int nk = K >> 6;           // K / 64

    // global row pointers (one 128B row per thread per tile)
    const __nv_bfloat16* pAh = Ah + (size_t)(bm + tid) * K;
    const __nv_bfloat16* pAl = Al + (size_t)(bm + tid) * K;
    const __nv_bfloat16* pBh = Bh + (size_t)(bn + tid) * K;
    const __nv_bfloat16* pBl = Bl + (size_t)(bn + tid) * K;

#if HAS_TCGEN05
    // ======================= tcgen05 path =======================
    if (wid == 0) tc_alloc(tptr_u, 128);
    if (tid == 0) { mbar_init(mbar_u, 1); mbar_init(mbar_u + 8, 1); }
    __syncthreads();
    uint32_t tmem;
    asm volatile("ld.shared.b32 %0, [%1];" : "=r"(tmem) : "r"(tptr_u));

    int ph0 = 0, ph1 = 0;
    for (int i = 0; i < nk; i++) {
        const int b = i & 1;
        if (i >= 2) {
            if (b == 0) { mbar_wait(mbar_u, ph0);     ph0 ^= 1; }
            else        { mbar_wait(mbar_u + 8, ph1); ph1 ^= 1; }
        }
        __syncthreads();
        {
            const int k0 = i << 6;
            char* bufA_h = tile_p + b * GEMM_BUF_BYTES;
            char* bufA_l = bufA_h + GEMM_TILE_BYTES;
            char* bufB_h = bufA_l + GEMM_TILE_BYTES;
            char* bufB_l = bufB_h + GEMM_TILE_BYTES;
            const uint4* sAh = (const uint4*)(pAh + k0);
            const uint4* sAl = (const uint4*)(pAl + k0);
            const uint4* sBh = (const uint4*)(pBh + k0);
            const uint4* sBl = (const uint4*)(pBl + k0);
#pragma unroll
            for (int j = 0; j < 8; j++) {
                uint32_t off = (uint32_t)(tid * 128 + j * 16);
                uint32_t sw  = off ^ ((off >> 3) & 0x70u);
                *(uint4*)(bufA_h + sw) = sAh[j];
                *(uint4*)(bufA_l + sw) = sAl[j];
                *(uint4*)(bufB_h + sw) = sBh[j];
                *(uint4*)(bufB_l + sw) = sBl[j];
            }
        }
        fence_proxy_async_shared();
        __syncthreads();

        if (wid == 0) {
            if (elect_one()) {
                const uint32_t base = tile_u + (uint32_t)b * GEMM_BUF_BYTES;
                const uint64_t dAh = MK_DESC(base);
                const uint64_t dAl = MK_DESC(base + GEMM_TILE_BYTES);
                const uint64_t dBh = MK_DESC(base + 2 * GEMM_TILE_BYTES);
                const uint64_t dBl = MK_DESC(base + 3 * GEMM_TILE_BYTES);
#pragma unroll
                for (int k = 0; k < 4; k++)
                    tc_mma_f16_ss(tmem, dAh + k * 2, dBh + k * 2, GEMM_IDESC, !(i == 0 && k == 0));
#pragma unroll
                for (int k = 0; k < 4; k++)
                    tc_mma_f16_ss(tmem, dAh + k * 2, dBl + k * 2, GEMM_IDESC, true);
#pragma unroll
                for (int k = 0; k < 4; k++)
                    tc_mma_f16_ss(tmem, dAl + k * 2, dBh + k * 2, GEMM_IDESC, true);
                tc_commit(mbar_u + (uint32_t)b * 8);
            }
        }
    }

    mbar_wait(mbar_u, ph0);
    mbar_wait(mbar_u + 8, ph1);
    tc_fence_after();

    {
        float* crow = C + (size_t)(bm + wid * 32 + lane) * N + bn;
#pragma unroll
        for (int c = 0; c < 4; c++) {
            uint32_t r[32];
            tc_ld_x32(r, tmem + c * 32);
            tc_wait_ld();
            tc_fence_before();
#pragma unroll
            for (int j = 0; j < 8; j++) {
                float4 o = make_float4(__uint_as_float(r[4 * j]),     __uint_as_float(r[4 * j + 1]),
                                       __uint_as_float(r[4 * j + 2]), __uint_as_float(r[4 * j + 3]));
                *(float4*)(crow + c * 32 + 4 * j) = o;
            }
        }
    }

    __syncthreads();
    if (wid == 0) {
        tc_relinquish();
        tc_dealloc(tmem, 128);
    }
#else
    // ======================= mma.sync fallback =======================
    (void)tptr_u; (void)mbar_u;
    float acc[2][16][4];
#pragma unroll
    for (int mi = 0; mi < 2; mi++)
#pragma unroll
        for (int j = 0; j < 16; j++)
#pragma unroll
            for (int q = 0; q < 4; q++) acc[mi][j][q] = 0.f;

    const int lr = lane >> 2;          // 0..7
    const int lc = (lane & 3) << 2;    // byte offset 0,4,8,12

    for (int i = 0; i < nk; i++) {
        const int b = i & 1;
        __syncthreads();
        {
            const int k0 = i << 6;
            char* bufA_h = tile_p + b * GEMM_BUF_BYTES;
            char* bufA_l = bufA_h + GEMM_TILE_BYTES;
            char* bufB_h = bufA_l + GEMM_TILE_BYTES;
            char* bufB_l = bufB_h + GEMM_TILE_BYTES;
            const uint4* sAh = (const uint4*)(pAh + k0);
            const uint4* sAl = (const uint4*)(pAl + k0);
            const uint4* sBh = (const uint4*)(pBh + k0);
            const uint4* sBl = (const uint4*)(pBl + k0);
#pragma unroll
            for (int j = 0; j < 8; j++) {
                uint32_t off = (uint32_t)(tid * 128 + j * 16);
                uint32_t sw  = off ^ ((off >> 3) & 0x70u);
                *(uint4*)(bufA_h + sw) = sAh[j];
                *(uint4*)(bufA_l + sw) = sAl[j];
                *(uint4*)(bufB_h + sw) = sBh[j];
                *(uint4*)(bufB_l + sw) = sBl[j];
            }
        }
        __syncthreads();

        const char* bAh = tile_p + b * GEMM_BUF_BYTES;
        const char* bAl = bAh + GEMM_TILE_BYTES;
        const char* bBh = bAl + GEMM_TILE_BYTES;
        const char* bBl = bBh + GEMM_TILE_BYTES;

#pragma unroll
        for (int ks = 0; ks < 4; ks++) {
            const int kb = ks * 32 + lc;
            uint32_t ah[2][4], al[2][4];
#pragma unroll
            for (int mi = 0; mi < 2; mi++) {
                const int r0 = wid * 32 + mi * 16 + lr;
                ah[mi][0] = lds_sw(bAh, r0,     kb);
                ah[mi][1] = lds_sw(bAh, r0 + 8, kb);
                ah[mi][2] = lds_sw(bAh, r0,     kb + 16);
                ah[mi][3] = lds_sw(bAh, r0 + 8, kb + 16);
                al[mi][0] = lds_sw(bAl, r0,     kb);
                al[mi][1] = lds_sw(bAl, r0 + 8, kb);
                al[mi][2] = lds_sw(bAl, r0,     kb + 16);
                al[mi][3] = lds_sw(bAl, r0 + 8, kb + 16);
            }
#pragma unroll
            for (int j = 0; j < 16; j++) {
                const int n0 = j * 8 + lr;
                uint32_t bh[2], bl[2];
                bh[0] = lds_sw(bBh, n0, kb);
                bh[1] = lds_sw(bBh, n0, kb + 16);
                bl[0] = lds_sw(bBl, n0, kb);
                bl[1] = lds_sw(bBl, n0, kb + 16);
                mma_bf16(acc[0][j], ah[0], bh);
                mma_bf16(acc[1][j], ah[1], bh);
                mma_bf16(acc[0][j], ah[0], bl);
                mma_bf16(acc[1][j], ah[1], bl);
                mma_bf16(acc[0][j], al[0], bh);
                mma_bf16(acc[1][j], al[1], bh);
            }
        }
    }

    // store: acc[mi][j] -> rows bm+wid*32+mi*16+{lr,lr+8}, cols bn+j*8+2*(lane&3)
#pragma unroll
    for (int mi = 0; mi < 2; mi++) {
        const int r0 = bm + wid * 32 + mi * 16 + lr;
#pragma unroll
        for (int j = 0; j < 16; j++) {
            const int col = bn + j * 8 + ((lane & 3) << 1);
            *(float2*)(C + (size_t)r0 * N + col)       = make_float2(acc[mi][j][0], acc[mi][j][1]);
            *(float2*)(C + (size_t)(r0 + 8) * N + col) = make_float2(acc[mi][j][2], acc[mi][j][3]);
        }
    }
#endif
}

// ---------------------------------------------------------------------------
// RMSNorm: out[row] = in[row] * rsqrt(mean(in^2)+eps) * w
// ---------------------------------------------------------------------------
__global__ __launch_bounds__(256) void rmsnorm_kernel(
    const float* __restrict__ in, const float* __restrict__ w,
    float* __restrict__ out)
{
    const int row  = blockIdx.x;
    const int base = threadIdx.x * 8;
    const float* r = in + (size_t)row * DDIM;

    float v[8];
    *(float4*)(v)     = *(const float4*)(r + base);
    *(float4*)(v + 4) = *(const float4*)(r + base + 4);

    float ss = 0.f;
#pragma unroll
    for (int i = 0; i < 8; i++) ss += v[i] * v[i];
#pragma unroll
    for (int o = 16; o > 0; o >>= 1) ss += __shfl_xor_sync(0xffffffffu, ss, o);

    __shared__ float red[8];
    __shared__ float sscale;
    if ((threadIdx.x & 31) == 0) red[threadIdx.x >> 5] = ss;
    __syncthreads();
    if (threadIdx.x == 0) {
        float t = 0.f;
#pragma unroll
        for (int i = 0; i < 8; i++) t += red[i];
        sscale = rsqrtf(t / (float)DDIM + EPSV);
    }
    __syncthreads();
    const float sc = sscale;

    float o8[8];
#pragma unroll
    for (int i = 0; i < 8; i++) o8[i] = v[i] * sc * w[base + i];
    float* op = out + (size_t)row * DDIM + base;
    *(float4*)(op)     = *(float4*)(o8);
    *(float4*)(op + 4) = *(float4*)(o8 + 4);
}

// ---------------------------------------------------------------------------
// RMSNorm of (ff + residual), writes final output
// ---------------------------------------------------------------------------
__global__ __launch_bounds__(256) void rms_resid_out_kernel(
    const float* __restrict__ ff, const float* __restrict__ res,
    const float* __restrict__ w, float* __restrict__ out)
{
    const int row  = blockIdx.x;
    const int base = threadIdx.x * 8;
    const float* f = ff  + (size_t)row * DDIM;
    const float* r = res + (size_t)row * DDIM;

    float4 a0 = *(const float4*)(f + base);
    float4 a1 = *(const float4*)(f + base + 4);
    float4 b0 = *(const float4*)(r + base);
    float4 b1 = *(const float4*)(r + base + 4);

    float v[8];
    v[0] = a0.x + b0.x; v[1] = a0.y + b0.y; v[2] = a0.z + b0.z; v[3] = a0.w + b0.w;
    v[4] = a1.x + b1.x; v[5] = a1.y + b1.y; v[6] = a1.z + b1.z; v[7] = a1.w + b1.w;

    float ss = 0.f;
#pragma unroll
    for (int i = 0; i < 8; i++) ss += v[i] * v[i];
#pragma unroll
    for (int o = 16; o > 0; o >>= 1) ss += __shfl_xor_sync(0xffffffffu, ss, o);

    __shared__ float red[8];
    __shared__ float sscale;
    if ((threadIdx.x & 31) == 0) red[threadIdx.x >> 5] = ss;
    __syncthreads();
    if (threadIdx.x == 0) {
        float t = 0.f;
#pragma unroll
        for (int i = 0; i < 8; i++) t += red[i];
        sscale = rsqrtf(t / (float)DDIM + EPSV);
    }
    __syncthreads();
    const float sc = sscale;

    float o8[8];
#pragma unroll
    for (int i = 0; i < 8; i++) o8[i] = v[i] * sc * w[base + i];
    float* op = out + (size_t)row * DDIM + base;
    *(float4*)(op)     = *(float4*)(o8);
    *(float4*)(op + 4) = *(float4*)(o8 + 4);
}

// ---------------------------------------------------------------------------
// SiLU-mul:  h1 = silu(h1) * h3
// ---------------------------------------------------------------------------
__global__ __launch_bounds__(256) void silu_mul_kernel(
    float* __restrict__ h1, const float* __restrict__ h3, int n4)
{
    const int i = blockIdx.x * blockDim.x + threadIdx.x;
    if (i >= n4) return;
    float4 a = ((float4*)h1)[i];
    float4 b = ((const float4*)h3)[i];
    a.x = a.x * (1.f / (1.f + __expf(-a.x))) * b.x;
    a.y = a.y * (1.f / (1.f + __expf(-a.y))) * b.y;
    a.z = a.z * (1.f / (1.f + __expf(-a.z))) * b.z;
    a.w = a.w * (1.f / (1.f + __expf(-a.w))) * b.w;
    ((float4*)h1)[i] = a;
}

// ---------------------------------------------------------------------------
// Flash attention (fp32, non-tensorcore) — unchanged from passing R4 kernel.
// ---------------------------------------------------------------------------
#define FLASH_SMEM ((64*132 + 64*132 + 64*128 + 64*65) * 4)

__global__ __launch_bounds__(256, 1) void flash_kernel(
    const float* __restrict__ Qg, const float* __restrict__ Kg,
    const float* __restrict__ Vg, float* __restrict__ Og)
{
    extern __shared__ float sm[];
    float* sQ = sm;                  // [64][132]
    float* sK = sm + 64 * 132;       // [64][132]
    float* sV = sK + 64 * 132;       // [64][128]
    float* sP = sV + 64 * 128;       // [64][65]

    const int tid = threadIdx.x;
    const int tx  = tid & 15;
    const int ty  = tid >> 4;
    const int q0  = blockIdx.x * 64;
    const int h   = blockIdx.y;
    const int b   = blockIdx.z;
    const size_t rowbase = (size_t)b * SS;
    const float scale = 0.0883883476483184405f;   // 1/sqrt(128)

    {
        const float* Qp = Qg + (rowbase + q0) * DDIM + h * HDIM;
#pragma unroll
        for (int li = tid; li < 64 * 32; li += 256) {
            int r = li >> 5, c4 = li & 31;
            *(float4*)(sQ + r * 132 + c4 * 4) =
                *(const float4*)(Qp + (size_t)r * DDIM + c4 * 4);
        }
    }

    float m_i[4], l_i[4], o[4][8];
#pragma unroll
    for (int i = 0; i < 4; i++) {
        m_i[i] = -1e30f;
        l_i[i] = 0.f;
#pragma unroll
        for (int d = 0; d < 8; d++) o[i][d] = 0.f;
    }

    for (int t = 0; t < SS / 64; t++) {
        const float* Kp = Kg + (rowbase + t * 64) * DDIM + h * HDIM;
        const float* Vp = Vg + (rowbase + t * 64) * DDIM + h * HDIM;

        __syncthreads();
#pragma unroll
        for (int li = tid; li < 64 * 32; li += 256) {
            int r = li >> 5, c4 = li & 31;
            *(float4*)(sK + r * 132 + c4 * 4) =
                *(const float4*)(Kp + (size_t)r * DDIM + c4 * 4);
            *(float4*)(sV + r * 128 + c4 * 4) =
                *(const float4*)(Vp + (size_t)r * DDIM + c4 * 4);
        }
        __syncthreads();

        float s[4][4];
#pragma unroll
        for (int i = 0; i < 4; i++)
#pragma unroll
            for (int j = 0; j < 4; j++) s[i][j] = 0.f;

#pragma unroll 4
        for (int c4 = 0; c4 < 32; c4++) {
            float4 qv[4], kv[4];
#pragma unroll
            for (int i = 0; i < 4; i++)
                qv[i] = *(const float4*)(sQ + (i * 16 + ty) * 132 + c4 * 4);
#pragma unroll
            for (int j = 0; j < 4; j++)
                kv[j] = *(const float4*)(sK + (j * 16 + tx) * 132 + c4 * 4);
#pragma unroll
            for (int i = 0; i < 4; i++)
#pragma unroll
                for (int j = 0; j < 4; j++)
                    s[i][j] += qv[i].x * kv[j].x + qv[i].y * kv[j].y +
                               qv[i].z * kv[j].z + qv[i].w * kv[j].w;
        }

#pragma unroll
        for (int i = 0; i < 4; i++) {
            float mx = -1e30f;
#pragma unroll
            for (int j = 0; j < 4; j++) {
                s[i][j] *= scale;
                mx = fmaxf(mx, s[i][j]);
            }
#pragma unroll
            for (int w = 1; w < 16; w <<= 1)
                mx = fmaxf(mx, __shfl_xor_sync(0xffffffffu, mx, w));
            const float mnew  = fmaxf(m_i[i], mx);
            const float alpha = __expf(m_i[i] - mnew);
            float rs = 0.f;
#pragma unroll
            for (int j = 0; j < 4; j++) {
                float p = __expf(s[i][j] - mnew);
                sP[(i * 16 + ty) * 65 + j * 16 + tx] = p;
                rs += p;
            }
#pragma unroll
            for (int w = 1; w < 16; w <<= 1)
                rs += __shfl_xor_sync(0xffffffffu, rs, w);
            l_i[i] = l_i[i] * alpha + rs;
            m_i[i] = mnew;
#pragma unroll
            for (int d = 0; d < 8; d++) o[i][d] *= alpha;
        }
        __syncthreads();

#pragma unroll 4
        for (int j = 0; j < 64; j++) {
            float4 v0 = *(const float4*)(sV + j * 128 + tx * 4);
            float4 v1 = *(const float4*)(sV + j * 128 + 64 + tx * 4);
#pragma unroll
            for (int i = 0; i < 4; i++) {
                const float p = sP[(i * 16 + ty) * 65 + j];
                o[i][0] += p * v0.x; o[i][1] += p * v0.y;
                o[i][2] += p * v0.z; o[i][3] += p * v0.w;
                o[i][4] += p * v1.x; o[i][5] += p * v1.y;
                o[i][6] += p * v1.z; o[i][7] += p * v1.w;
            }
        }
    }

#pragma unroll
    for (int i = 0; i < 4; i++) {
        const float inv = 1.f / l_i[i];
        float* op = Og + (rowbase + q0 + i * 16 + ty) * DDIM + h * HDIM;
        float4 r0 = make_float4(o[i][0] * inv, o[i][1] * inv, o[i][2] * inv, o[i][3] * inv);
        float4 r1 = make_float4(o[i][4] * inv, o[i][5] * inv, o[i][6] * inv, o[i][7] * inv);
        *(float4*)(op + tx * 4)      = r0;
        *(float4*)(op + 64 + tx * 4) = r1;
    }
}

// ---------------------------------------------------------------------------
// Host orchestration
// ---------------------------------------------------------------------------
extern "C" void kernel_launch(void* const* d_in, const int* in_sizes, int n_in,
                              void* d_out, int out_size)
{
    (void)in_sizes; (void)n_in; (void)out_size;

    const float* x           = (const float*)d_in[0];
    const float* y           = (const float*)d_in[1];
    const float* attn_norm_w = (const float*)d_in[2];
    const float* wq[2]  = {(const float*)d_in[3],  (const float*)d_in[7]};
    const float* wk[2]  = {(const float*)d_in[4],  (const float*)d_in[8]};
    const float* wv[2]  = {(const float*)d_in[5],  (const float*)d_in[9]};
    const float* wo[2]  = {(const float*)d_in[6],  (const float*)d_in[10]};
    const float* w1[2]  = {(const float*)d_in[11], (const float*)d_in[15]};
    const float* w2[2]  = {(const float*)d_in[12], (const float*)d_in[16]};
    const float* w3[2]  = {(const float*)d_in[13], (const float*)d_in[17]};
    const float* fnw[2] = {(const float*)d_in[14], (const float*)d_in[18]};
    float* out = (float*)d_out;

    float *xn, *yn, *q, *k, *v, *att, *proj, *h1, *h3, *ff;
    cudaGetSymbolAddress((void**)&xn,   g_xn);
    cudaGetSymbolAddress((void**)&yn,   g_yn);
    cudaGetSymbolAddress((void**)&q,    g_q);
    cudaGetSymbolAddress((void**)&k,    g_k);
    cudaGetSymbolAddress((void**)&v,    g_v);
    cudaGetSymbolAddress((void**)&att,  g_att);
    cudaGetSymbolAddress((void**)&proj, g_proj);
    cudaGetSymbolAddress((void**)&h1,   g_h1);
    cudaGetSymbolAddress((void**)&h3,   g_h3);
    cudaGetSymbolAddress((void**)&ff,   g_ff);

    __nv_bfloat16 *ah, *al, *wh, *wl;
    cudaGetSymbolAddress((void**)&ah, g_act_hi);
    cudaGetSymbolAddress((void**)&al, g_act_lo);
    cudaGetSymbolAddress((void**)&wh, g_wgt_hi);
    cudaGetSymbolAddress((void**)&wl, g_wgt_lo);

    cudaFuncSetAttribute(flash_kernel,
                         cudaFuncAttributeMaxDynamicSharedMemorySize, FLASH_SMEM);
    cudaFuncSetAttribute(gemm_bf16x3,
                         cudaFuncAttributeMaxDynamicSharedMemorySize, GEMM_SMEM);

    // Pre-norms (shared attn_norm weight)
    rmsnorm_kernel<<<BSR, 256>>>(x, attn_norm_w, xn);
    rmsnorm_kernel<<<BSR, 256>>>(y, attn_norm_w, yn);

    const dim3 gAttn(SS / 64, HH, BB);
    const int  n4 = BSR * FFD / 4;

    auto split = [](const float* src, __nv_bfloat16* hi, __nv_bfloat16* lo, int n) {
        int n4s = n / 4;
        split_bf16_kernel<<<(n4s + 255) / 256, 256>>>(src, hi, lo, n4s);
    };
    auto gemm = [&](const __nv_bfloat16* Ah_, const __nv_bfloat16* Al_,
                    const __nv_bfloat16* Bh_, const __nv_bfloat16* Bl_,
                    float* C, int M, int N, int K) {
        dim3 g(N / 128, M / 128);
        gemm_bf16x3<<<g, 128, GEMM_SMEM>>>(Ah_, Al_, Bh_, Bl_, C, M, N, K);
    };

    for (int p = 0; p < 2; p++) {
        const float* qin   = (p == 0) ? xn : yn;
        const float* kvin  = (p == 0) ? yn : xn;
        const float* resid = (p == 0) ? x  : y;

        // Q projection
        split(qin, ah, al, BSR * DDIM);
        split(wq[p], wh, wl, DDIM * DDIM);
        gemm(ah, al, wh, wl, q, BSR, DDIM, DDIM);

        // K, V projections (same activation, different weights)
        split(kvin, ah, al, BSR * DDIM);
        split(wk[p], wh, wl, DDIM * DDIM);
        gemm(ah, al, wh, wl, k, BSR, DDIM, DDIM);
        split(wv[p], wh, wl, DDIM * DDIM);
        gemm(ah, al, wh, wl, v, BSR, DDIM, DDIM);

        flash_kernel<<<gAttn, 256, FLASH_SMEM>>>(q, k, v, att);

        // output projection
        split(att, ah, al, BSR * DDIM);
        split(wo[p], wh, wl, DDIM * DDIM);
        gemm(ah, al, wh, wl, proj, BSR, DDIM, DDIM);

        // FFN
        split(proj, ah, al, BSR * DDIM);
        split(w1[p], wh, wl, FFD * DDIM);
        gemm(ah, al, wh, wl, h1, BSR, FFD, DDIM);
        split(w3[p], wh, wl, FFD * DDIM);
        gemm(ah, al, wh, wl, h3, BSR, FFD, DDIM);

        silu_mul_kernel<<<(n4 + 255) / 256, 256>>>(h1, h3, n4);

        split(h1, ah, al, BSR * FFD);
        split(w2[p], wh, wl, DDIM * FFD);
        gemm(ah, al, wh, wl, ff, BSR, DDIM, FFD);

        rms_resid_out_kernel<<<BSR, 256>>>(ff, resid, fnw[p],
                                           out + (size_t)p * BSR * DDIM);
    }
}